// round 14
// baseline (speedup 1.0000x reference)
#include <cuda_runtime.h>
#include <cuda_fp16.h>
#include <cstdint>

// Problem constants: N=100000, IN=512, OUT=256, E=3.2M
#define IN_DIM  512
#define OUT_DIM 256
#define MAX_N   100000
#define MAX_E   3200000
#define SCAN_CHUNK 1024
#define SCAN_BLOCKS ((MAX_N + SCAN_CHUNK - 1) / SCAN_CHUNK)   // 98

// Scratch (device globals; g_count relies on static zero-init + re-zero in scan)
__device__ __half g_support[(size_t)MAX_N * OUT_DIM];  // 51.2 MB fp16
__device__ __half g_wh[(size_t)OUT_DIM * IN_DIM];      // w^T [256][512] fp16, K-major
__device__ int    g_count[MAX_N];                      // ALWAYS zero between runs
__device__ int    g_offset[MAX_N + 1];
__device__ int    g_cursor[MAX_N];
__device__ int2   g_edges[MAX_E];
// decoupled-lookback state (flags re-zeroed by prelude every run)
__device__ int    g_flag[SCAN_BLOCKS];     // 0=invalid, 1=aggregate, 2=inclusive
__device__ int    g_aggval[SCAN_BLOCKS];
__device__ int    g_incval[SCAN_BLOCKS];

// ===========================================================================
// PTX helpers
// ===========================================================================
__device__ __forceinline__ uint32_t smem_u32(const void* p) {
    uint32_t a;
    asm("{ .reg .u64 t; cvta.to.shared.u64 t, %1; cvt.u32.u64 %0, t; }"
        : "=r"(a) : "l"(p));
    return a;
}

__device__ __forceinline__ void cp_async16(uint32_t dst, const void* src) {
    asm volatile("cp.async.cg.shared.global [%0], [%1], 16;"
                 :: "r"(dst), "l"(src) : "memory");
}
#define CP_COMMIT() asm volatile("cp.async.commit_group;" ::: "memory")
#define CP_WAIT0()  asm volatile("cp.async.wait_group 0;" ::: "memory")

__device__ __forceinline__ void ldsm_x4(uint32_t* r, uint32_t addr) {
    asm volatile("ldmatrix.sync.aligned.m8n8.x4.shared.b16 {%0,%1,%2,%3}, [%4];"
                 : "=r"(r[0]), "=r"(r[1]), "=r"(r[2]), "=r"(r[3]) : "r"(addr));
}

__device__ __forceinline__ void mma16816(float* c, const uint32_t* a, const uint32_t* b) {
    asm volatile(
        "mma.sync.aligned.m16n8k16.row.col.f32.f16.f16.f32 "
        "{%0,%1,%2,%3}, {%4,%5,%6,%7}, {%8,%9}, {%0,%1,%2,%3};"
        : "+f"(c[0]), "+f"(c[1]), "+f"(c[2]), "+f"(c[3])
        : "r"(a[0]), "r"(a[1]), "r"(a[2]), "r"(a[3]), "r"(b[0]), "r"(b[1]));
}

// ===========================================================================
// Prelude: weight transpose+convert (blocks 0-127) || histogram (rest).
// Thread 0 of the first hist block also re-zeroes the 98 lookback flags.
// ===========================================================================
#define TRANS_BLOCKS 128          // (OUT/32) * (IN/32) = 8*16
#define HIST_BLOCKS  2048

__global__ __launch_bounds__(256)
void prelude_kernel(const float* __restrict__ w, const int* __restrict__ rows,
                    int E)
{
    __shared__ float tile[32][33];
    const int tid = threadIdx.x;
    if (blockIdx.x < TRANS_BLOCKS) {
        int n0 = (blockIdx.x & 7) * 32;
        int k0 = (blockIdx.x >> 3) * 32;
        int tx = tid & 31;
        int ty = tid >> 5;              // 0..7
        #pragma unroll
        for (int i = 0; i < 4; i++)
            tile[ty + 8 * i][tx] = w[(size_t)(k0 + ty + 8 * i) * OUT_DIM + n0 + tx];
        __syncthreads();
        #pragma unroll
        for (int i = 0; i < 4; i++)
            g_wh[(size_t)(n0 + ty + 8 * i) * IN_DIM + k0 + tx]
                = __float2half(tile[tx][ty + 8 * i]);
    } else {
        const int hb   = blockIdx.x - TRANS_BLOCKS;
        // first hist block: re-zero lookback flags (98 ints)
        if (hb == 0 && tid < SCAN_BLOCKS) g_flag[tid] = 0;
        const int qid  = hb * 256 + tid;
        const int span = HIST_BLOCKS * 256;
        const int nquads = E >> 2;
        for (int q = qid; q < nquads; q += span) {
            int4 r = *(const int4*)(rows + q * 4);
            atomicAdd(&g_count[r.x], 1);
            atomicAdd(&g_count[r.y], 1);
            atomicAdd(&g_count[r.z], 1);
            atomicAdd(&g_count[r.w], 1);
        }
        if (qid == 0)
            for (int j = nquads * 4; j < E; j++) atomicAdd(&g_count[rows[j]], 1);
    }
}

// ===========================================================================
// Single-pass decoupled-lookback scan: g_count -> g_offset/g_cursor,
// re-zeroes g_count. 98 blocks, all co-resident (<=148 SMs) -> spin is safe.
// ===========================================================================
__device__ __forceinline__ int block_excl_scan(int v, int* warp_sums, int* total)
{
    const int lane = threadIdx.x & 31;
    const int wid  = threadIdx.x >> 5;
    const int nw   = blockDim.x >> 5;

    int s = v;
    #pragma unroll
    for (int off = 1; off < 32; off <<= 1) {
        int t = __shfl_up_sync(0xFFFFFFFFu, s, off);
        if (lane >= off) s += t;
    }
    if (lane == 31) warp_sums[wid] = s;
    __syncthreads();
    if (wid == 0) {
        int ws = (lane < nw) ? warp_sums[lane] : 0;
        #pragma unroll
        for (int off = 1; off < 32; off <<= 1) {
            int t = __shfl_up_sync(0xFFFFFFFFu, ws, off);
            if (lane >= off) ws += t;
        }
        if (lane < nw) warp_sums[lane] = ws;
    }
    __syncthreads();
    *total = warp_sums[nw - 1];
    return (wid > 0 ? warp_sums[wid - 1] : 0) + (s - v);
}

__global__ __launch_bounds__(SCAN_CHUNK)
void scan_kernel(int N)
{
    __shared__ int warp_sums[32];
    __shared__ int s_prefix;

    const int b   = blockIdx.x;
    const int tid = threadIdx.x;
    const int i   = b * SCAN_CHUNK + tid;

    int v = (i < N) ? g_count[i] : 0;
    int total;
    int excl = block_excl_scan(v, warp_sums, &total);

    if (tid == 0) {
        // publish aggregate
        g_aggval[b] = total;
        __threadfence();
        if (b == 0) {
            g_incval[0] = total;
            __threadfence();
            atomicExch(&g_flag[0], 2);
            s_prefix = 0;
        } else {
            atomicExch(&g_flag[b], 1);
            // lookback
            int prefix = 0;
            int j = b - 1;
            while (true) {
                int f;
                do { f = atomicAdd(&g_flag[j], 0); } while (f == 0);
                __threadfence();
                if (f == 2) { prefix += g_incval[j]; break; }
                prefix += g_aggval[j];
                j--;
            }
            g_incval[b] = prefix + total;
            __threadfence();
            atomicExch(&g_flag[b], 2);
            s_prefix = prefix;
        }
        if (b == gridDim.x - 1)
            g_offset[N] = ((b == 0) ? 0 : s_prefix) + total;
    }
    __syncthreads();

    if (i < N) {
        int o = s_prefix + excl;
        g_offset[i] = o;
        g_cursor[i] = o;
        g_count[i]  = 0;          // free re-zero for the next invocation
    }
}

// ===========================================================================
// Fused: HMMA GEMM || reorder (3:1 interleave). (unchanged from R13)
// GEMM: CTA tile 128(M) x 256(N), 512 threads, 16 warps x (32x64), BK=32.
// ===========================================================================
#define GSTRIDE 40                 // halves per SMEM row (32 data + 8 pad)
#define NSTAGE  16                 // 512 / 32
#define OFF_A0  0
#define OFF_A1  (128 * GSTRIDE * 2)                // 10240
#define OFF_B0  (2 * 128 * GSTRIDE * 2)            // 20480
#define OFF_B1  (OFF_B0 + 256 * GSTRIDE * 2)       // 40960
#define GEMM_SMEM (OFF_B1 + 256 * GSTRIDE * 2)     // 61440

__global__ __launch_bounds__(512, 1)
void gemm_reorder_kernel(const float* __restrict__ x,
                         const int*   __restrict__ active,
                         const int*   __restrict__ rows,
                         const int*   __restrict__ cols,
                         const float* __restrict__ vals,
                         int N, int E, int ngroups)
{
    extern __shared__ char dsm[];
    const int tid = threadIdx.x;
    const int g   = blockIdx.x >> 2;
    const int sub = blockIdx.x & 3;

    if (sub == 3) {
        const int span = ngroups * 512;
        for (int i = g * 512 + tid; i < E; i += span) {
            int r = rows[i];
            int pos = atomicAdd(&g_cursor[r], 1);
            g_edges[pos] = make_int2(cols[i], __float_as_int(vals[i]));
        }
        return;
    }

    const int gemm_bid = g * 3 + sub;
    const int block_row = gemm_bid * 128;
    if (block_row >= N) return;

    const int wid  = tid >> 5;
    const int lane = tid & 31;

    const int mbase = (wid & 3) * 32;
    const int nbase = (wid >> 2) * 64;

    float acc[2][8][4];
    #pragma unroll
    for (int mt = 0; mt < 2; mt++)
        #pragma unroll
        for (int nt = 0; nt < 8; nt++)
            #pragma unroll
            for (int j = 0; j < 4; j++)
                acc[mt][nt][j] = 0.0f;

    const int a_r0 = tid >> 3;
    const int a_r1 = (tid + 512) >> 3;
    const int a_q  = tid & 7;
    int ag0 = block_row + a_r0; if (ag0 >= N) ag0 = N - 1;
    int ag1 = block_row + a_r1; if (ag1 >= N) ag1 = N - 1;
    const float* ap0 = x + (size_t)ag0 * IN_DIM + a_q * 4;
    const float* ap1 = x + (size_t)ag1 * IN_DIM + a_q * 4;

    int b_n[2], b_q[2];
    const __half* bp[2];
    #pragma unroll
    for (int i = 0; i < 2; i++) {
        int c = tid + 512 * i;
        b_n[i] = c >> 2;
        b_q[i] = c & 3;
        bp[i] = g_wh + (size_t)b_n[i] * IN_DIM + b_q[i] * 8;
    }

    const uint32_t aS[2] = { smem_u32(dsm + OFF_A0), smem_u32(dsm + OFF_A1) };
    const uint32_t bS[2] = { smem_u32(dsm + OFF_B0), smem_u32(dsm + OFF_B1) };

    auto load_B = [&](int s, int buf) {
        const int k0 = s * 32;
        #pragma unroll
        for (int i = 0; i < 2; i++)
            cp_async16(bS[buf] + (b_n[i] * GSTRIDE + b_q[i] * 8) * 2, bp[i] + k0);
        CP_COMMIT();
    };

    auto store_A = [&](int buf, const float4 av0, const float4 av1) {
        __half* dA = (__half*)(dsm + (buf ? OFF_A1 : OFF_A0));
        __half* d0 = dA + a_r0 * GSTRIDE + a_q * 4;
        __half* d1 = dA + a_r1 * GSTRIDE + a_q * 4;
        *(__half2*)(d0)     = __float22half2_rn(make_float2(av0.x, av0.y));
        *(__half2*)(d0 + 2) = __float22half2_rn(make_float2(av0.z, av0.w));
        *(__half2*)(d1)     = __float22half2_rn(make_float2(av1.x, av1.y));
        *(__half2*)(d1 + 2) = __float22half2_rn(make_float2(av1.z, av1.w));
    };

    {
        load_B(0, 0);
        float4 av0 = *(const float4*)(ap0);
        float4 av1 = *(const float4*)(ap1);
        store_A(0, av0, av1);
        CP_WAIT0();
        __syncthreads();
    }

    int buf = 0;
    for (int s = 0; s < NSTAGE; s++) {
        float4 av0, av1;
        if (s < NSTAGE - 1) {
            const int k0n = (s + 1) * 32;
            av0 = *(const float4*)(ap0 + k0n);
            av1 = *(const float4*)(ap1 + k0n);
            load_B(s + 1, buf ^ 1);
        }

        const int ar   = lane & 7;
        const int amid = (lane >> 3) & 1;
        const int akh  = lane >> 4;
        #pragma unroll
        for (int ks = 0; ks < 2; ks++) {
            uint32_t afrag[2][4];
            #pragma unroll
            for (int mt = 0; mt < 2; mt++) {
                uint32_t addr = aS[buf] +
                    ((mbase + mt * 16 + amid * 8 + ar) * GSTRIDE + ks * 16 + akh * 8) * 2;
                ldsm_x4(afrag[mt], addr);
            }
            #pragma unroll
            for (int np = 0; np < 4; np++) {
                uint32_t bfrag[4];
                uint32_t baddr = bS[buf] +
                    ((nbase + np * 16 + (lane >> 4) * 8 + (lane & 7)) * GSTRIDE
                     + ks * 16 + ((lane >> 3) & 1) * 8) * 2;
                ldsm_x4(bfrag, baddr);
                #pragma unroll
                for (int mt = 0; mt < 2; mt++) {
                    mma16816(acc[mt][np * 2],     afrag[mt], &bfrag[0]);
                    mma16816(acc[mt][np * 2 + 1], afrag[mt], &bfrag[2]);
                }
            }
        }

        if (s < NSTAGE - 1) {
            store_A(buf ^ 1, av0, av1);
            CP_WAIT0();
            __syncthreads();
            buf ^= 1;
        }
    }

    const bool act = (*active) != 0;
    #pragma unroll
    for (int mt = 0; mt < 2; mt++) {
        const int gm0 = block_row + mbase + mt * 16 + (lane >> 2);
        const int gm1 = gm0 + 8;
        #pragma unroll
        for (int nt = 0; nt < 8; nt++) {
            const int gn = nbase + nt * 8 + (lane & 3) * 2;
            float c0 = acc[mt][nt][0], c1 = acc[mt][nt][1];
            float c2 = acc[mt][nt][2], c3 = acc[mt][nt][3];
            if (act) { c0 = tanhf(c0); c1 = tanhf(c1); c2 = tanhf(c2); c3 = tanhf(c3); }
            if (gm0 < N)
                *(__half2*)&g_support[(size_t)gm0 * OUT_DIM + gn]
                    = __float22half2_rn(make_float2(c0, c1));
            if (gm1 < N)
                *(__half2*)&g_support[(size_t)gm1 * OUT_DIM + gn]
                    = __float22half2_rn(make_float2(c2, c3));
        }
    }
}

// ===========================================================================
// Gather SpMM: streaming cache hints -- edges via __ldcs (evict-first),
// output via __stcs (streaming store) so neither displaces the L2-resident
// support array.
// ===========================================================================
__device__ __forceinline__ void fma8_h(const uint4 p, float v, float* acc)
{
    float2 f0 = __half22float2(*(const __half2*)&p.x);
    float2 f1 = __half22float2(*(const __half2*)&p.y);
    float2 f2 = __half22float2(*(const __half2*)&p.z);
    float2 f3 = __half22float2(*(const __half2*)&p.w);
    acc[0] = fmaf(v, f0.x, acc[0]);
    acc[1] = fmaf(v, f0.y, acc[1]);
    acc[2] = fmaf(v, f1.x, acc[2]);
    acc[3] = fmaf(v, f1.y, acc[3]);
    acc[4] = fmaf(v, f2.x, acc[4]);
    acc[5] = fmaf(v, f2.y, acc[5]);
    acc[6] = fmaf(v, f3.x, acc[6]);
    acc[7] = fmaf(v, f3.y, acc[7]);
}

__global__ __launch_bounds__(256)
void gather_kernel(float* __restrict__ out, int N)
{
    int warp = (blockIdx.x * blockDim.x + threadIdx.x) >> 5;
    int lane = threadIdx.x & 31;
    if (warp >= N) return;

    int beg = g_offset[warp];
    int end = g_offset[warp + 1];

    float acc[8];
    #pragma unroll
    for (int j = 0; j < 8; j++) acc[j] = 0.0f;

    int e = beg;
    for (; e + 1 < end; e += 2) {
        int2 ed0 = __ldcs(&g_edges[e]);
        int2 ed1 = __ldcs(&g_edges[e + 1]);
        const uint4* s0 = (const uint4*)(g_support + (size_t)ed0.x * OUT_DIM);
        const uint4* s1 = (const uint4*)(g_support + (size_t)ed1.x * OUT_DIM);
        uint4 p0 = s0[lane];
        uint4 p1 = s1[lane];
        fma8_h(p0, __int_as_float(ed0.y), acc);
        fma8_h(p1, __int_as_float(ed1.y), acc);
    }
    if (e < end) {
        int2 ed = __ldcs(&g_edges[e]);
        const uint4* s = (const uint4*)(g_support + (size_t)ed.x * OUT_DIM);
        uint4 p = s[lane];
        fma8_h(p, __int_as_float(ed.y), acc);
    }

    float4* dst = (float4*)(out + (size_t)warp * OUT_DIM + lane * 8);
    __stcs(dst,     make_float4(acc[0], acc[1], acc[2], acc[3]));
    __stcs(dst + 1, make_float4(acc[4], acc[5], acc[6], acc[7]));
}

// ===========================================================================
// Launch (4 kernels total)
// ===========================================================================
extern "C" void kernel_launch(void* const* d_in, const int* in_sizes, int n_in,
                              void* d_out, int out_size)
{
    const float* x      = (const float*)d_in[0];
    const float* w      = (const float*)d_in[1];
    const int*   erows  = (const int*)d_in[2];
    const int*   ecols  = (const int*)d_in[3];
    const float* evals  = (const float*)d_in[4];
    const int*   active = (const int*)d_in[5];
    float*       out    = (float*)d_out;

    const int N = in_sizes[0] / IN_DIM;
    const int E = in_sizes[2];
    const int nsb = (N + SCAN_CHUNK - 1) / SCAN_CHUNK;

    cudaFuncSetAttribute(gemm_reorder_kernel,
                         cudaFuncAttributeMaxDynamicSharedMemorySize, GEMM_SMEM);

    // 1) prelude: weight transpose+convert || histogram (+ flag re-zero)
    prelude_kernel<<<TRANS_BLOCKS + HIST_BLOCKS, 256>>>(w, erows, E);

    // 2) single-pass decoupled-lookback scan (re-zeroes g_count)
    scan_kernel<<<nsb, SCAN_CHUNK>>>(N);

    // 3) fused GEMM (BM=128, single N pass) || reorder (3:1 interleaved)
    int gemm_blocks = (N + 127) / 128;          // 782
    int ngroups = (gemm_blocks + 2) / 3;        // 261
    gemm_reorder_kernel<<<ngroups * 4, 512, GEMM_SMEM>>>(
        x, active, erows, ecols, evals, N, E, ngroups);

    // 4) gather SpMM
    int gblocks = (N * 32 + 255) / 256;
    gather_kernel<<<gblocks, 256>>>(out, N);
}

// round 15
// speedup vs baseline: 1.1084x; 1.1084x over previous
#include <cuda_runtime.h>
#include <cuda_fp16.h>
#include <cstdint>

// Problem constants: N=100000, IN=512, OUT=256, E=3.2M
#define IN_DIM  512
#define OUT_DIM 256
#define MAX_N   100000
#define MAX_E   3200000
#define SCAN_CHUNK 1024
#define SCAN_BLOCKS ((MAX_N + SCAN_CHUNK - 1) / SCAN_CHUNK)   // 98

// Scratch (device globals; g_count relies on static zero-init + re-zero in scan)
__device__ __half g_support[(size_t)MAX_N * OUT_DIM];  // 51.2 MB fp16
__device__ __half g_wh[(size_t)OUT_DIM * IN_DIM];      // w^T [256][512] fp16, K-major
__device__ int    g_count[MAX_N];                      // ALWAYS zero between runs
__device__ int    g_offset[MAX_N + 1];
__device__ int    g_cursor[MAX_N];
__device__ int2   g_edges[MAX_E];
// decoupled-lookback state (flags re-zeroed by prelude every run)
__device__ int    g_flag[SCAN_BLOCKS];     // 0=invalid, 1=aggregate, 2=inclusive
__device__ int    g_aggval[SCAN_BLOCKS];
__device__ int    g_incval[SCAN_BLOCKS];

// ===========================================================================
// PTX helpers
// ===========================================================================
__device__ __forceinline__ uint32_t smem_u32(const void* p) {
    uint32_t a;
    asm("{ .reg .u64 t; cvta.to.shared.u64 t, %1; cvt.u32.u64 %0, t; }"
        : "=r"(a) : "l"(p));
    return a;
}

__device__ __forceinline__ void cp_async16(uint32_t dst, const void* src) {
    asm volatile("cp.async.cg.shared.global [%0], [%1], 16;"
                 :: "r"(dst), "l"(src) : "memory");
}
#define CP_COMMIT() asm volatile("cp.async.commit_group;" ::: "memory")
#define CP_WAIT0()  asm volatile("cp.async.wait_group 0;" ::: "memory")

__device__ __forceinline__ void ldsm_x4(uint32_t* r, uint32_t addr) {
    asm volatile("ldmatrix.sync.aligned.m8n8.x4.shared.b16 {%0,%1,%2,%3}, [%4];"
                 : "=r"(r[0]), "=r"(r[1]), "=r"(r[2]), "=r"(r[3]) : "r"(addr));
}

__device__ __forceinline__ void mma16816(float* c, const uint32_t* a, const uint32_t* b) {
    asm volatile(
        "mma.sync.aligned.m16n8k16.row.col.f32.f16.f16.f32 "
        "{%0,%1,%2,%3}, {%4,%5,%6,%7}, {%8,%9}, {%0,%1,%2,%3};"
        : "+f"(c[0]), "+f"(c[1]), "+f"(c[2]), "+f"(c[3])
        : "r"(a[0]), "r"(a[1]), "r"(a[2]), "r"(a[3]), "r"(b[0]), "r"(b[1]));
}

// ===========================================================================
// Prelude: weight transpose+convert (blocks 0-127) || histogram (rest).
// Thread 0 of the first hist block also re-zeroes the 98 lookback flags.
// ===========================================================================
#define TRANS_BLOCKS 128          // (OUT/32) * (IN/32) = 8*16
#define HIST_BLOCKS  2048

__global__ __launch_bounds__(256)
void prelude_kernel(const float* __restrict__ w, const int* __restrict__ rows,
                    int E)
{
    __shared__ float tile[32][33];
    const int tid = threadIdx.x;
    if (blockIdx.x < TRANS_BLOCKS) {
        int n0 = (blockIdx.x & 7) * 32;
        int k0 = (blockIdx.x >> 3) * 32;
        int tx = tid & 31;
        int ty = tid >> 5;              // 0..7
        #pragma unroll
        for (int i = 0; i < 4; i++)
            tile[ty + 8 * i][tx] = w[(size_t)(k0 + ty + 8 * i) * OUT_DIM + n0 + tx];
        __syncthreads();
        #pragma unroll
        for (int i = 0; i < 4; i++)
            g_wh[(size_t)(n0 + ty + 8 * i) * IN_DIM + k0 + tx]
                = __float2half(tile[tx][ty + 8 * i]);
    } else {
        const int hb   = blockIdx.x - TRANS_BLOCKS;
        if (hb == 0 && tid < SCAN_BLOCKS) g_flag[tid] = 0;
        const int qid  = hb * 256 + tid;
        const int span = HIST_BLOCKS * 256;
        const int nquads = E >> 2;
        for (int q = qid; q < nquads; q += span) {
            int4 r = *(const int4*)(rows + q * 4);
            atomicAdd(&g_count[r.x], 1);
            atomicAdd(&g_count[r.y], 1);
            atomicAdd(&g_count[r.z], 1);
            atomicAdd(&g_count[r.w], 1);
        }
        if (qid == 0)
            for (int j = nquads * 4; j < E; j++) atomicAdd(&g_count[rows[j]], 1);
    }
}

// ===========================================================================
// Single-pass decoupled-lookback scan (98 co-resident blocks)
// ===========================================================================
__device__ __forceinline__ int block_excl_scan(int v, int* warp_sums, int* total)
{
    const int lane = threadIdx.x & 31;
    const int wid  = threadIdx.x >> 5;
    const int nw   = blockDim.x >> 5;

    int s = v;
    #pragma unroll
    for (int off = 1; off < 32; off <<= 1) {
        int t = __shfl_up_sync(0xFFFFFFFFu, s, off);
        if (lane >= off) s += t;
    }
    if (lane == 31) warp_sums[wid] = s;
    __syncthreads();
    if (wid == 0) {
        int ws = (lane < nw) ? warp_sums[lane] : 0;
        #pragma unroll
        for (int off = 1; off < 32; off <<= 1) {
            int t = __shfl_up_sync(0xFFFFFFFFu, ws, off);
            if (lane >= off) ws += t;
        }
        if (lane < nw) warp_sums[lane] = ws;
    }
    __syncthreads();
    *total = warp_sums[nw - 1];
    return (wid > 0 ? warp_sums[wid - 1] : 0) + (s - v);
}

__global__ __launch_bounds__(SCAN_CHUNK)
void scan_kernel(int N)
{
    __shared__ int warp_sums[32];
    __shared__ int s_prefix;

    const int b   = blockIdx.x;
    const int tid = threadIdx.x;
    const int i   = b * SCAN_CHUNK + tid;

    int v = (i < N) ? g_count[i] : 0;
    int total;
    int excl = block_excl_scan(v, warp_sums, &total);

    if (tid == 0) {
        g_aggval[b] = total;
        __threadfence();
        if (b == 0) {
            g_incval[0] = total;
            __threadfence();
            atomicExch(&g_flag[0], 2);
            s_prefix = 0;
        } else {
            atomicExch(&g_flag[b], 1);
            int prefix = 0;
            int j = b - 1;
            while (true) {
                int f;
                do { f = atomicAdd(&g_flag[j], 0); } while (f == 0);
                __threadfence();
                if (f == 2) { prefix += g_incval[j]; break; }
                prefix += g_aggval[j];
                j--;
            }
            g_incval[b] = prefix + total;
            __threadfence();
            atomicExch(&g_flag[b], 2);
            s_prefix = prefix;
        }
        if (b == gridDim.x - 1)
            g_offset[N] = ((b == 0) ? 0 : s_prefix) + total;
    }
    __syncthreads();

    if (i < N) {
        int o = s_prefix + excl;
        g_offset[i] = o;
        g_cursor[i] = o;
        g_count[i]  = 0;
    }
}

// ===========================================================================
// Fused: HMMA GEMM || reorder (3:1 interleave).
// GEMM: CTA tile 128(M) x 256(N), 512 threads, 16 warps x (32x64), BK=32.
// ===========================================================================
#define GSTRIDE 40
#define NSTAGE  16
#define OFF_A0  0
#define OFF_A1  (128 * GSTRIDE * 2)
#define OFF_B0  (2 * 128 * GSTRIDE * 2)
#define OFF_B1  (OFF_B0 + 256 * GSTRIDE * 2)
#define GEMM_SMEM (OFF_B1 + 256 * GSTRIDE * 2)     // 61440

__global__ __launch_bounds__(512, 1)
void gemm_reorder_kernel(const float* __restrict__ x,
                         const int*   __restrict__ active,
                         const int*   __restrict__ rows,
                         const int*   __restrict__ cols,
                         const float* __restrict__ vals,
                         int N, int E, int ngroups)
{
    extern __shared__ char dsm[];
    const int tid = threadIdx.x;
    const int g   = blockIdx.x >> 2;
    const int sub = blockIdx.x & 3;

    if (sub == 3) {
        const int span = ngroups * 512;
        for (int i = g * 512 + tid; i < E; i += span) {
            int r = rows[i];
            int pos = atomicAdd(&g_cursor[r], 1);
            g_edges[pos] = make_int2(cols[i], __float_as_int(vals[i]));
        }
        return;
    }

    const int gemm_bid = g * 3 + sub;
    const int block_row = gemm_bid * 128;
    if (block_row >= N) return;

    const int wid  = tid >> 5;
    const int lane = tid & 31;

    const int mbase = (wid & 3) * 32;
    const int nbase = (wid >> 2) * 64;

    float acc[2][8][4];
    #pragma unroll
    for (int mt = 0; mt < 2; mt++)
        #pragma unroll
        for (int nt = 0; nt < 8; nt++)
            #pragma unroll
            for (int j = 0; j < 4; j++)
                acc[mt][nt][j] = 0.0f;

    const int a_r0 = tid >> 3;
    const int a_r1 = (tid + 512) >> 3;
    const int a_q  = tid & 7;
    int ag0 = block_row + a_r0; if (ag0 >= N) ag0 = N - 1;
    int ag1 = block_row + a_r1; if (ag1 >= N) ag1 = N - 1;
    const float* ap0 = x + (size_t)ag0 * IN_DIM + a_q * 4;
    const float* ap1 = x + (size_t)ag1 * IN_DIM + a_q * 4;

    int b_n[2], b_q[2];
    const __half* bp[2];
    #pragma unroll
    for (int i = 0; i < 2; i++) {
        int c = tid + 512 * i;
        b_n[i] = c >> 2;
        b_q[i] = c & 3;
        bp[i] = g_wh + (size_t)b_n[i] * IN_DIM + b_q[i] * 8;
    }

    const uint32_t aS[2] = { smem_u32(dsm + OFF_A0), smem_u32(dsm + OFF_A1) };
    const uint32_t bS[2] = { smem_u32(dsm + OFF_B0), smem_u32(dsm + OFF_B1) };

    auto load_B = [&](int s, int buf) {
        const int k0 = s * 32;
        #pragma unroll
        for (int i = 0; i < 2; i++)
            cp_async16(bS[buf] + (b_n[i] * GSTRIDE + b_q[i] * 8) * 2, bp[i] + k0);
        CP_COMMIT();
    };

    auto store_A = [&](int buf, const float4 av0, const float4 av1) {
        __half* dA = (__half*)(dsm + (buf ? OFF_A1 : OFF_A0));
        __half* d0 = dA + a_r0 * GSTRIDE + a_q * 4;
        __half* d1 = dA + a_r1 * GSTRIDE + a_q * 4;
        *(__half2*)(d0)     = __float22half2_rn(make_float2(av0.x, av0.y));
        *(__half2*)(d0 + 2) = __float22half2_rn(make_float2(av0.z, av0.w));
        *(__half2*)(d1)     = __float22half2_rn(make_float2(av1.x, av1.y));
        *(__half2*)(d1 + 2) = __float22half2_rn(make_float2(av1.z, av1.w));
    };

    {
        load_B(0, 0);
        float4 av0 = *(const float4*)(ap0);
        float4 av1 = *(const float4*)(ap1);
        store_A(0, av0, av1);
        CP_WAIT0();
        __syncthreads();
    }

    int buf = 0;
    for (int s = 0; s < NSTAGE; s++) {
        float4 av0, av1;
        if (s < NSTAGE - 1) {
            const int k0n = (s + 1) * 32;
            av0 = *(const float4*)(ap0 + k0n);
            av1 = *(const float4*)(ap1 + k0n);
            load_B(s + 1, buf ^ 1);
        }

        const int ar   = lane & 7;
        const int amid = (lane >> 3) & 1;
        const int akh  = lane >> 4;
        #pragma unroll
        for (int ks = 0; ks < 2; ks++) {
            uint32_t afrag[2][4];
            #pragma unroll
            for (int mt = 0; mt < 2; mt++) {
                uint32_t addr = aS[buf] +
                    ((mbase + mt * 16 + amid * 8 + ar) * GSTRIDE + ks * 16 + akh * 8) * 2;
                ldsm_x4(afrag[mt], addr);
            }
            #pragma unroll
            for (int np = 0; np < 4; np++) {
                uint32_t bfrag[4];
                uint32_t baddr = bS[buf] +
                    ((nbase + np * 16 + (lane >> 4) * 8 + (lane & 7)) * GSTRIDE
                     + ks * 16 + ((lane >> 3) & 1) * 8) * 2;
                ldsm_x4(bfrag, baddr);
                #pragma unroll
                for (int mt = 0; mt < 2; mt++) {
                    mma16816(acc[mt][np * 2],     afrag[mt], &bfrag[0]);
                    mma16816(acc[mt][np * 2 + 1], afrag[mt], &bfrag[2]);
                }
            }
        }

        if (s < NSTAGE - 1) {
            store_A(buf ^ 1, av0, av1);
            CP_WAIT0();
            __syncthreads();
            buf ^= 1;
        }
    }

    const bool act = (*active) != 0;
    #pragma unroll
    for (int mt = 0; mt < 2; mt++) {
        const int gm0 = block_row + mbase + mt * 16 + (lane >> 2);
        const int gm1 = gm0 + 8;
        #pragma unroll
        for (int nt = 0; nt < 8; nt++) {
            const int gn = nbase + nt * 8 + (lane & 3) * 2;
            float c0 = acc[mt][nt][0], c1 = acc[mt][nt][1];
            float c2 = acc[mt][nt][2], c3 = acc[mt][nt][3];
            if (act) { c0 = tanhf(c0); c1 = tanhf(c1); c2 = tanhf(c2); c3 = tanhf(c3); }
            if (gm0 < N)
                *(__half2*)&g_support[(size_t)gm0 * OUT_DIM + gn]
                    = __float22half2_rn(make_float2(c0, c1));
            if (gm1 < N)
                *(__half2*)&g_support[(size_t)gm1 * OUT_DIM + gn]
                    = __float22half2_rn(make_float2(c2, c3));
        }
    }
}

// ===========================================================================
// Gather SpMM: x4 unrolled -- 4 independent 128B/warp support loads in
// flight before any FMA consumption (latency-bound fix per R14 profile).
// Plain loads/stores (cache hints regressed in R14).
// ===========================================================================
__device__ __forceinline__ void fma8_h(const uint4 p, float v, float* acc)
{
    float2 f0 = __half22float2(*(const __half2*)&p.x);
    float2 f1 = __half22float2(*(const __half2*)&p.y);
    float2 f2 = __half22float2(*(const __half2*)&p.z);
    float2 f3 = __half22float2(*(const __half2*)&p.w);
    acc[0] = fmaf(v, f0.x, acc[0]);
    acc[1] = fmaf(v, f0.y, acc[1]);
    acc[2] = fmaf(v, f1.x, acc[2]);
    acc[3] = fmaf(v, f1.y, acc[3]);
    acc[4] = fmaf(v, f2.x, acc[4]);
    acc[5] = fmaf(v, f2.y, acc[5]);
    acc[6] = fmaf(v, f3.x, acc[6]);
    acc[7] = fmaf(v, f3.y, acc[7]);
}

__global__ __launch_bounds__(256)
void gather_kernel(float* __restrict__ out, int N)
{
    int warp = (blockIdx.x * blockDim.x + threadIdx.x) >> 5;
    int lane = threadIdx.x & 31;
    if (warp >= N) return;

    int beg = g_offset[warp];
    int end = g_offset[warp + 1];

    float acc[8];
    #pragma unroll
    for (int j = 0; j < 8; j++) acc[j] = 0.0f;

    int e = beg;
    // x4 unroll: all 4 support loads issued before any consumption
    for (; e + 3 < end; e += 4) {
        int2 ed0 = g_edges[e];
        int2 ed1 = g_edges[e + 1];
        int2 ed2 = g_edges[e + 2];
        int2 ed3 = g_edges[e + 3];
        uint4 p0 = ((const uint4*)(g_support + (size_t)ed0.x * OUT_DIM))[lane];
        uint4 p1 = ((const uint4*)(g_support + (size_t)ed1.x * OUT_DIM))[lane];
        uint4 p2 = ((const uint4*)(g_support + (size_t)ed2.x * OUT_DIM))[lane];
        uint4 p3 = ((const uint4*)(g_support + (size_t)ed3.x * OUT_DIM))[lane];
        fma8_h(p0, __int_as_float(ed0.y), acc);
        fma8_h(p1, __int_as_float(ed1.y), acc);
        fma8_h(p2, __int_as_float(ed2.y), acc);
        fma8_h(p3, __int_as_float(ed3.y), acc);
    }
    for (; e < end; e++) {
        int2 ed = g_edges[e];
        uint4 p = ((const uint4*)(g_support + (size_t)ed.x * OUT_DIM))[lane];
        fma8_h(p, __int_as_float(ed.y), acc);
    }

    float* dst = out + (size_t)warp * OUT_DIM + lane * 8;
    *(float4*)(dst)     = make_float4(acc[0], acc[1], acc[2], acc[3]);
    *(float4*)(dst + 4) = make_float4(acc[4], acc[5], acc[6], acc[7]);
}

// ===========================================================================
// Launch (4 kernels total)
// ===========================================================================
extern "C" void kernel_launch(void* const* d_in, const int* in_sizes, int n_in,
                              void* d_out, int out_size)
{
    const float* x      = (const float*)d_in[0];
    const float* w      = (const float*)d_in[1];
    const int*   erows  = (const int*)d_in[2];
    const int*   ecols  = (const int*)d_in[3];
    const float* evals  = (const float*)d_in[4];
    const int*   active = (const int*)d_in[5];
    float*       out    = (float*)d_out;

    const int N = in_sizes[0] / IN_DIM;
    const int E = in_sizes[2];
    const int nsb = (N + SCAN_CHUNK - 1) / SCAN_CHUNK;

    cudaFuncSetAttribute(gemm_reorder_kernel,
                         cudaFuncAttributeMaxDynamicSharedMemorySize, GEMM_SMEM);

    // 1) prelude: weight transpose+convert || histogram (+ flag re-zero)
    prelude_kernel<<<TRANS_BLOCKS + HIST_BLOCKS, 256>>>(w, erows, E);

    // 2) single-pass decoupled-lookback scan (re-zeroes g_count)
    scan_kernel<<<nsb, SCAN_CHUNK>>>(N);

    // 3) fused GEMM (BM=128, single N pass) || reorder (3:1 interleaved)
    int gemm_blocks = (N + 127) / 128;          // 782
    int ngroups = (gemm_blocks + 2) / 3;        // 261
    gemm_reorder_kernel<<<ngroups * 4, 512, GEMM_SMEM>>>(
        x, active, erows, ecols, evals, N, E, ngroups);

    // 4) gather SpMM (x4 unrolled)
    int gblocks = (N * 32 + 255) / 256;
    gather_kernel<<<gblocks, 256>>>(out, N);
}